// round 1
// baseline (speedup 1.0000x reference)
#include <cuda_runtime.h>
#include <cstdint>

#define BB   8
#define NN   4096
#define CC   512
#define HH   256
#define NCLS 1000
#define MTOT (BB*NN)   // 32768

// ---------------- device scratch (no allocation allowed) ----------------
__device__ float g_prevsum[BB][CC];
__device__ float g_rowsum[MTOT];
__device__ float g_rowsumsq[MTOT];
__device__ float g_rstd[MTOT];
__device__ float g_tb[BB];        // sum_r rstd_r * mu_r
__device__ float g_Rb[BB];        // sum_r rstd_r
__device__ float g_v[BB][CC];     // sum_r rstd_r * feat[r, c]
__device__ float g_pooled[BB][CC];
__device__ float g_h1[BB][HH];
__device__ float g_h2[BB][HH];

// ---------------- init (zero accumulators) ----------------
__global__ void k_init() {
    int i = blockIdx.x * blockDim.x + threadIdx.x;
    if (i < MTOT) { g_rowsum[i] = 0.f; g_rowsumsq[i] = 0.f; }
    if (i < BB * CC) { ((float*)g_prevsum)[i] = 0.f; ((float*)g_v)[i] = 0.f; }
    if (i < BB) { g_tb[i] = 0.f; g_Rb[i] = 0.f; }
}

// ---------------- column-sum of prev_out over tokens ----------------
__global__ void k_prev(const float* __restrict__ prev) {
    int b = blockIdx.y;
    int c = threadIdx.x;               // 512 threads
    int n0 = blockIdx.x * 128;         // grid.x = 32
    const float* p = prev + ((size_t)(b * NN + n0)) * CC + c;
    float s = 0.f;
#pragma unroll 4
    for (int n = 0; n < 128; ++n) s += p[(size_t)n * CC];
    atomicAdd(&g_prevsum[b][c], s);
}

// ---------------- fused tf32 GEMM -> per-row sum / sumsq ----------------
// proj[r,d] = feat[r,:] . W[d,:] + pb[d]; accumulate sum_d proj, sum_d proj^2
#define TM 128
#define TN 128
#define KC 16
#define PAD 20   // 80B rows: 16B-aligned for cp.async, conflict-free lds

__global__ void __launch_bounds__(256, 2)
k_gemm(const float* __restrict__ A, const float* __restrict__ W,
       const float* __restrict__ pb) {
    __shared__ float As[2][TM][PAD];
    __shared__ float Bs[2][TN][PAD];
    __shared__ float pbs[TN];

    const int tid  = threadIdx.x;
    const int row0 = blockIdx.x * TM;
    const int col0 = blockIdx.y * TN;

    if (tid < TN) pbs[tid] = pb[col0 + tid];

    auto fill = [&](int s, int kc) {
        int k0 = kc * KC;
#pragma unroll
        for (int i = 0; i < 2; i++) {
            int idx = tid + i * 256;             // 512 chunks of 16B
            int r = idx >> 2, seg = idx & 3;
            uint32_t dst = (uint32_t)__cvta_generic_to_shared(&As[s][r][seg * 4]);
            const float* src = A + (size_t)(row0 + r) * CC + k0 + seg * 4;
            asm volatile("cp.async.cg.shared.global [%0], [%1], 16;\n"
                         :: "r"(dst), "l"(src));
        }
#pragma unroll
        for (int i = 0; i < 2; i++) {
            int idx = tid + i * 256;
            int r = idx >> 2, seg = idx & 3;
            uint32_t dst = (uint32_t)__cvta_generic_to_shared(&Bs[s][r][seg * 4]);
            const float* src = W + (size_t)(col0 + r) * CC + k0 + seg * 4;
            asm volatile("cp.async.cg.shared.global [%0], [%1], 16;\n"
                         :: "r"(dst), "l"(src));
        }
    };

    fill(0, 0); asm volatile("cp.async.commit_group;\n");
    fill(1, 1); asm volatile("cp.async.commit_group;\n");

    const int warp = tid >> 5, lane = tid & 31;
    const int g = lane >> 2, q = lane & 3;
    const int wm = warp >> 1, wn = warp & 1;   // 4 x 2 warp grid
    const int rbase = wm * 32, cbase = wn * 64;

    float acc[2][8][4];
#pragma unroll
    for (int mt = 0; mt < 2; mt++)
#pragma unroll
        for (int nt = 0; nt < 8; nt++)
#pragma unroll
            for (int j = 0; j < 4; j++) acc[mt][nt][j] = 0.f;

    const int NKC = CC / KC;   // 32
    for (int kc = 0; kc < NKC; ++kc) {
        int s = kc & 1;
        asm volatile("cp.async.wait_group 1;\n");
        __syncthreads();
#pragma unroll
        for (int kt = 0; kt < 2; kt++) {
            int k = kt * 8;
            uint32_t a[2][4], bf[8][2];
#pragma unroll
            for (int mt = 0; mt < 2; mt++) {
                int rb = rbase + mt * 16;
                // +0x1000: integer round-to-nearest into tf32 mantissa (bias-free)
                a[mt][0] = __float_as_uint(As[s][rb + g    ][k + q    ]) + 0x1000u;
                a[mt][1] = __float_as_uint(As[s][rb + g + 8][k + q    ]) + 0x1000u;
                a[mt][2] = __float_as_uint(As[s][rb + g    ][k + q + 4]) + 0x1000u;
                a[mt][3] = __float_as_uint(As[s][rb + g + 8][k + q + 4]) + 0x1000u;
            }
#pragma unroll
            for (int nt = 0; nt < 8; nt++) {
                int cb = cbase + nt * 8;
                bf[nt][0] = __float_as_uint(Bs[s][cb + g][k + q    ]) + 0x1000u;
                bf[nt][1] = __float_as_uint(Bs[s][cb + g][k + q + 4]) + 0x1000u;
            }
#pragma unroll
            for (int mt = 0; mt < 2; mt++)
#pragma unroll
                for (int nt = 0; nt < 8; nt++)
                    asm volatile(
                        "mma.sync.aligned.m16n8k8.row.col.f32.tf32.tf32.f32 "
                        "{%0,%1,%2,%3},{%4,%5,%6,%7},{%8,%9},{%0,%1,%2,%3};"
                        : "+f"(acc[mt][nt][0]), "+f"(acc[mt][nt][1]),
                          "+f"(acc[mt][nt][2]), "+f"(acc[mt][nt][3])
                        : "r"(a[mt][0]), "r"(a[mt][1]), "r"(a[mt][2]), "r"(a[mt][3]),
                          "r"(bf[nt][0]), "r"(bf[nt][1]));
        }
        __syncthreads();
        if (kc + 2 < NKC) fill(s, kc + 2);
        asm volatile("cp.async.commit_group;\n");
    }

    // Epilogue: add bias, reduce each row's 512 outputs to (sum, sumsq).
#pragma unroll
    for (int mt = 0; mt < 2; mt++) {
        float s0 = 0.f, q0 = 0.f, s1 = 0.f, q1 = 0.f;
#pragma unroll
        for (int nt = 0; nt < 8; nt++) {
            float pb0 = pbs[cbase + nt * 8 + 2 * q];
            float pb1 = pbs[cbase + nt * 8 + 2 * q + 1];
            float v;
            v = acc[mt][nt][0] + pb0; s0 += v; q0 += v * v;
            v = acc[mt][nt][1] + pb1; s0 += v; q0 += v * v;
            v = acc[mt][nt][2] + pb0; s1 += v; q1 += v * v;
            v = acc[mt][nt][3] + pb1; s1 += v; q1 += v * v;
        }
#pragma unroll
        for (int off = 1; off < 4; off <<= 1) {
            s0 += __shfl_xor_sync(0xffffffffu, s0, off);
            q0 += __shfl_xor_sync(0xffffffffu, q0, off);
            s1 += __shfl_xor_sync(0xffffffffu, s1, off);
            q1 += __shfl_xor_sync(0xffffffffu, q1, off);
        }
        if (q == 0) {
            int r = row0 + rbase + mt * 16 + g;
            atomicAdd(&g_rowsum[r],       s0);
            atomicAdd(&g_rowsumsq[r],     q0);
            atomicAdd(&g_rowsum[r + 8],   s1);
            atomicAdd(&g_rowsumsq[r + 8], q1);
        }
    }
}

// ---------------- per-row LN stats, per-batch scalars ----------------
__global__ void k_stats() {
    int t = threadIdx.x;
    int r = blockIdx.x * 256 + t;
    float sum = g_rowsum[r], sq = g_rowsumsq[r];
    float mu  = sum * (1.f / CC);
    float var = sq * (1.f / CC) - mu * mu;
    float rstd = rsqrtf(var + 1e-5f);
    g_rstd[r] = rstd;

    __shared__ float sA[256], sB[256];
    sA[t] = rstd; sB[t] = rstd * mu;
    __syncthreads();
    for (int s = 128; s > 0; s >>= 1) {
        if (t < s) { sA[t] += sA[t + s]; sB[t] += sB[t + s]; }
        __syncthreads();
    }
    if (t == 0) {
        int b = r >> 12;   // 4096 rows per batch, blocks never straddle
        atomicAdd(&g_Rb[b], sA[0]);
        atomicAdd(&g_tb[b], sB[0]);
    }
}

// ---------------- v[b][c] = sum_n rstd * feat ----------------
__global__ void k_v(const float* __restrict__ feat) {
    int b = blockIdx.y;
    int c = threadIdx.x;
    int n0 = blockIdx.x * 128;
    const float* p  = feat + ((size_t)(b * NN + n0)) * CC + c;
    const float* rs = g_rstd + b * NN + n0;
    float s = 0.f;
#pragma unroll 4
    for (int n = 0; n < 128; ++n) s += rs[n] * p[(size_t)n * CC];
    atomicAdd(&g_v[b][c], s);
}

// ---------------- pooled[b][d] via GEMV with W ----------------
__global__ void k_pool(const float* __restrict__ W, const float* __restrict__ pb,
                       const float* __restrict__ lng, const float* __restrict__ lnb) {
    int warp = blockIdx.x * 8 + (threadIdx.x >> 5);   // 0..4095
    int lane = threadIdx.x & 31;
    int b = warp >> 9;
    int d = warp & 511;
    const float* wrow = W + (size_t)d * CC;
    const float* v = g_v[b];
    float s = 0.f;
#pragma unroll 4
    for (int c = lane; c < CC; c += 32) s += wrow[c] * v[c];
#pragma unroll
    for (int off = 16; off > 0; off >>= 1) s += __shfl_xor_sync(0xffffffffu, s, off);
    if (lane == 0) {
        float sv = s + g_Rb[b] * pb[d] - g_tb[b];
        g_pooled[b][d] = (g_prevsum[b][d] + lng[d] * sv) * (1.f / NN) + lnb[d];
    }
}

// ---------------- MLP head ----------------
__global__ void k_mlp1(const float* __restrict__ W1, const float* __restrict__ b1) {
    int warp = blockIdx.x * 8 + (threadIdx.x >> 5);   // 0..2047
    int lane = threadIdx.x & 31;
    int b = warp >> 8, i = warp & 255;
    const float* w = W1 + (size_t)i * CC;
    float s = 0.f;
#pragma unroll 4
    for (int c = lane; c < CC; c += 32) s += w[c] * g_pooled[b][c];
#pragma unroll
    for (int off = 16; off > 0; off >>= 1) s += __shfl_xor_sync(0xffffffffu, s, off);
    if (lane == 0) g_h1[b][i] = fmaxf(s + b1[i], 0.f);
}

__global__ void k_mlp2(const float* __restrict__ W2, const float* __restrict__ b2) {
    int warp = blockIdx.x * 8 + (threadIdx.x >> 5);
    int lane = threadIdx.x & 31;
    int b = warp >> 8, i = warp & 255;
    const float* w = W2 + (size_t)i * HH;
    float s = 0.f;
#pragma unroll
    for (int c = lane; c < HH; c += 32) s += w[c] * g_h1[b][c];
#pragma unroll
    for (int off = 16; off > 0; off >>= 1) s += __shfl_xor_sync(0xffffffffu, s, off);
    if (lane == 0) g_h2[b][i] = fmaxf(s + b2[i], 0.f);
}

__global__ void k_mlp3(const float* __restrict__ W3, const float* __restrict__ b3,
                       float* __restrict__ out) {
    int warp = blockIdx.x * 8 + (threadIdx.x >> 5);   // 0..7999
    int lane = threadIdx.x & 31;
    int b = warp / NCLS, j = warp % NCLS;
    const float* w = W3 + (size_t)j * HH;
    float s = 0.f;
#pragma unroll
    for (int c = lane; c < HH; c += 32) s += w[c] * g_h2[b][c];
#pragma unroll
    for (int off = 16; off > 0; off >>= 1) s += __shfl_xor_sync(0xffffffffu, s, off);
    if (lane == 0) out[b * NCLS + j] = s + b3[j];
}

// ---------------- launch ----------------
extern "C" void kernel_launch(void* const* d_in, const int* in_sizes, int n_in,
                              void* d_out, int out_size) {
    (void)in_sizes; (void)n_in; (void)out_size;
    const float* feat  = (const float*)d_in[0];
    const float* prev  = (const float*)d_in[1];
    // d_in[2], d_in[3] (positions) are provably unused: the gather is a row
    // permutation and all consumers are permutation-invariant.
    const float* projW = (const float*)d_in[4];
    const float* projb = (const float*)d_in[5];
    const float* lng   = (const float*)d_in[6];
    const float* lnb   = (const float*)d_in[7];
    const float* W1    = (const float*)d_in[8];
    const float* b1    = (const float*)d_in[9];
    const float* W2    = (const float*)d_in[10];
    const float* b2    = (const float*)d_in[11];
    const float* W3    = (const float*)d_in[12];
    const float* b3    = (const float*)d_in[13];
    float* out = (float*)d_out;

    k_init<<<MTOT / 256, 256>>>();
    k_prev<<<dim3(32, 8), 512>>>(prev);
    k_gemm<<<dim3(MTOT / TM, CC / TN), 256>>>(feat, projW, projb);
    k_stats<<<MTOT / 256, 256>>>();
    k_v<<<dim3(32, 8), 512>>>(feat);
    k_pool<<<512, 256>>>(projW, projb, lng, lnb);
    k_mlp1<<<256, 256>>>(W1, b1);
    k_mlp2<<<256, 256>>>(W2, b2);
    k_mlp3<<<1000, 256>>>(W3, b3, out);
}

// round 3
// speedup vs baseline: 1.3857x; 1.3857x over previous
#include <cuda_runtime.h>
#include <cuda_bf16.h>
#include <cstdint>

#define BB   8
#define NN   4096
#define CC   512
#define HH   256
#define NCLS 1000
#define MTOT (BB*NN)   // 32768

// ---------------- device scratch ----------------
__device__ __nv_bfloat16 g_featb[(size_t)MTOT * CC];  // 32 MB
__device__ __nv_bfloat16 g_Wb[(size_t)CC * CC];       // 512 KB
__device__ float g_prevsum[BB][CC];
__device__ float g_rowsum[MTOT];
__device__ float g_rowsumsq[MTOT];
__device__ float g_rstd[MTOT];
__device__ float g_tb[BB];
__device__ float g_Rb[BB];
__device__ float g_v[BB][CC];
__device__ float g_pooled[BB][CC];
__device__ float g_h1[BB][HH];
__device__ float g_h2[BB][HH];

// ---------------- init ----------------
__global__ void k_init() {
    int i = blockIdx.x * blockDim.x + threadIdx.x;
    if (i < MTOT) { g_rowsum[i] = 0.f; g_rowsumsq[i] = 0.f; }
    if (i < BB * CC) { ((float*)g_prevsum)[i] = 0.f; ((float*)g_v)[i] = 0.f; }
    if (i < BB) { g_tb[i] = 0.f; g_Rb[i] = 0.f; }
}

// ---------------- fp32 -> bf16 conversion (vectorized) ----------------
__global__ void k_cvt(const float* __restrict__ src, __nv_bfloat16* __restrict__ dst,
                      int n4) {
    int i = blockIdx.x * blockDim.x + threadIdx.x;
    if (i < n4) {
        float4 v = ((const float4*)src)[i];
        __nv_bfloat162 lo = __floats2bfloat162_rn(v.x, v.y);
        __nv_bfloat162 hi = __floats2bfloat162_rn(v.z, v.w);
        ((__nv_bfloat162*)dst)[2 * i]     = lo;
        ((__nv_bfloat162*)dst)[2 * i + 1] = hi;
    }
}

// ---------------- column-sum of prev_out ----------------
__global__ void k_prev(const float* __restrict__ prev) {
    int b = blockIdx.y;
    int c = threadIdx.x;
    int n0 = blockIdx.x * 128;
    const float* p = prev + ((size_t)(b * NN + n0)) * CC + c;
    float s = 0.f;
#pragma unroll 4
    for (int n = 0; n < 128; ++n) s += p[(size_t)n * CC];
    atomicAdd(&g_prevsum[b][c], s);
}

// ---------------- bf16 m16n8k16 GEMM -> per-row sum / sumsq ----------------
// CTA tile 128x128, K=512 in 16 chunks of 32 (bf16), 5-stage cp.async pipeline.
#define KC    32
#define NKC   16
#define STG   5
#define ROWB  80                      // 64B data + 16B pad: conflict-free
#define MATB  (128 * ROWB)            // 10240 per matrix per stage
#define STAGE_BYTES (2 * MATB)        // A + B
#define SMEM_NEED (STG * STAGE_BYTES + 512)

__global__ void __launch_bounds__(256, 2)
k_gemm(const float* __restrict__ pb) {
    extern __shared__ char sm[];
    float* pbs = (float*)(sm + STG * STAGE_BYTES);

    const int tid = threadIdx.x;
    const int row0 = blockIdx.x * 128, col0 = blockIdx.y * 128;
    if (tid < 128) pbs[tid] = pb[col0 + tid];

    uint32_t sbase;
    asm("{ .reg .u64 t; cvta.to.shared.u64 t, %1; cvt.u32.u64 %0, t; }"
        : "=r"(sbase) : "l"(sm));

    auto fill = [&](int j) {
        int stg = j % STG;
        int k0 = j * KC;
        uint32_t ab = sbase + stg * STAGE_BYTES;
        uint32_t bb = ab + MATB;
#pragma unroll
        for (int i = 0; i < 2; i++) {
            int id = tid + i * 256;           // 0..511
            int r = id >> 2, seg = id & 3;
            const __nv_bfloat16* sa = g_featb + (size_t)(row0 + r) * CC + k0 + seg * 8;
            const __nv_bfloat16* sb = g_Wb   + (size_t)(col0 + r) * CC + k0 + seg * 8;
            asm volatile("cp.async.cg.shared.global [%0], [%1], 16;"
                         :: "r"(ab + r * ROWB + seg * 16), "l"(sa));
            asm volatile("cp.async.cg.shared.global [%0], [%1], 16;"
                         :: "r"(bb + r * ROWB + seg * 16), "l"(sb));
        }
    };

#pragma unroll
    for (int j = 0; j < STG - 1; j++) {       // prefill 4 stages
        fill(j);
        asm volatile("cp.async.commit_group;");
    }

    const int warp = tid >> 5, lane = tid & 31;
    const int g = lane >> 2, q = lane & 3;
    const int wm = warp >> 1, wn = warp & 1;  // 4x2 warps
    const int rbase = wm * 32, cbase = wn * 64;

    float acc[2][8][4];
#pragma unroll
    for (int mt = 0; mt < 2; mt++)
#pragma unroll
        for (int nt = 0; nt < 8; nt++)
#pragma unroll
            for (int j = 0; j < 4; j++) acc[mt][nt][j] = 0.f;

    for (int kc = 0; kc < NKC; kc++) {
        asm volatile("cp.async.wait_group %0;" :: "n"(STG - 2));
        __syncthreads();
        const char* as = sm + (kc % STG) * STAGE_BYTES;
        const char* bs = as + MATB;
#pragma unroll
        for (int kt = 0; kt < 2; kt++) {
            int kb = kt * 32 + q * 4;         // byte offset of {2q,2q+1} bf16 pair
            uint32_t a[2][4], b[8][2];
#pragma unroll
            for (int mt = 0; mt < 2; mt++) {
                const char* r0p = as + (rbase + mt * 16 + g) * ROWB + kb;
                const char* r1p = r0p + 8 * ROWB;
                a[mt][0] = *(const uint32_t*)(r0p);
                a[mt][1] = *(const uint32_t*)(r1p);
                a[mt][2] = *(const uint32_t*)(r0p + 16);
                a[mt][3] = *(const uint32_t*)(r1p + 16);
            }
#pragma unroll
            for (int nt = 0; nt < 8; nt++) {
                const char* cp = bs + (cbase + nt * 8 + g) * ROWB + kb;
                b[nt][0] = *(const uint32_t*)(cp);
                b[nt][1] = *(const uint32_t*)(cp + 16);
            }
#pragma unroll
            for (int mt = 0; mt < 2; mt++)
#pragma unroll
                for (int nt = 0; nt < 8; nt++)
                    asm volatile(
                        "mma.sync.aligned.m16n8k16.row.col.f32.bf16.bf16.f32 "
                        "{%0,%1,%2,%3},{%4,%5,%6,%7},{%8,%9},{%0,%1,%2,%3};"
                        : "+f"(acc[mt][nt][0]), "+f"(acc[mt][nt][1]),
                          "+f"(acc[mt][nt][2]), "+f"(acc[mt][nt][3])
                        : "r"(a[mt][0]), "r"(a[mt][1]), "r"(a[mt][2]), "r"(a[mt][3]),
                          "r"(b[nt][0]), "r"(b[nt][1]));
        }
        __syncthreads();
        int jn = kc + STG - 1;
        if (jn < NKC) fill(jn);
        asm volatile("cp.async.commit_group;");
    }

    // Epilogue: add bias, reduce each row's 128 outputs to (sum, sumsq).
#pragma unroll
    for (int mt = 0; mt < 2; mt++) {
        float s0 = 0.f, q0 = 0.f, s1 = 0.f, q1 = 0.f;
#pragma unroll
        for (int nt = 0; nt < 8; nt++) {
            float pb0 = pbs[cbase + nt * 8 + 2 * q];
            float pb1 = pbs[cbase + nt * 8 + 2 * q + 1];
            float v;
            v = acc[mt][nt][0] + pb0; s0 += v; q0 += v * v;
            v = acc[mt][nt][1] + pb1; s0 += v; q0 += v * v;
            v = acc[mt][nt][2] + pb0; s1 += v; q1 += v * v;
            v = acc[mt][nt][3] + pb1; s1 += v; q1 += v * v;
        }
#pragma unroll
        for (int off = 1; off < 4; off <<= 1) {
            s0 += __shfl_xor_sync(0xffffffffu, s0, off);
            q0 += __shfl_xor_sync(0xffffffffu, q0, off);
            s1 += __shfl_xor_sync(0xffffffffu, s1, off);
            q1 += __shfl_xor_sync(0xffffffffu, q1, off);
        }
        if (q == 0) {
            int r = row0 + rbase + mt * 16 + g;
            atomicAdd(&g_rowsum[r],       s0);
            atomicAdd(&g_rowsumsq[r],     q0);
            atomicAdd(&g_rowsum[r + 8],   s1);
            atomicAdd(&g_rowsumsq[r + 8], q1);
        }
    }
}

// ---------------- per-row LN stats ----------------
__global__ void k_stats() {
    int t = threadIdx.x;
    int r = blockIdx.x * 256 + t;
    float sum = g_rowsum[r], sq = g_rowsumsq[r];
    float mu  = sum * (1.f / CC);
    float var = sq * (1.f / CC) - mu * mu;
    float rstd = rsqrtf(var + 1e-5f);
    g_rstd[r] = rstd;

    __shared__ float sA[256], sB[256];
    sA[t] = rstd; sB[t] = rstd * mu;
    __syncthreads();
    for (int s = 128; s > 0; s >>= 1) {
        if (t < s) { sA[t] += sA[t + s]; sB[t] += sB[t + s]; }
        __syncthreads();
    }
    if (t == 0) {
        int b = r >> 12;
        atomicAdd(&g_Rb[b], sA[0]);
        atomicAdd(&g_tb[b], sB[0]);
    }
}

// ---------------- v[b][c] = sum_n rstd * feat (fp32, exact) ----------------
__global__ void k_v(const float* __restrict__ feat) {
    int b = blockIdx.y;
    int c = threadIdx.x;
    int n0 = blockIdx.x * 128;
    const float* p  = feat + ((size_t)(b * NN + n0)) * CC + c;
    const float* rs = g_rstd + b * NN + n0;
    float s = 0.f;
#pragma unroll 4
    for (int n = 0; n < 128; ++n) s += rs[n] * p[(size_t)n * CC];
    atomicAdd(&g_v[b][c], s);
}

// ---------------- pooled via GEMV with W ----------------
__global__ void k_pool(const float* __restrict__ W, const float* __restrict__ pb,
                       const float* __restrict__ lng, const float* __restrict__ lnb) {
    int warp = blockIdx.x * 8 + (threadIdx.x >> 5);
    int lane = threadIdx.x & 31;
    int b = warp >> 9;
    int d = warp & 511;
    const float* wrow = W + (size_t)d * CC;
    const float* v = g_v[b];
    float s = 0.f;
#pragma unroll 4
    for (int c = lane; c < CC; c += 32) s += wrow[c] * v[c];
#pragma unroll
    for (int off = 16; off > 0; off >>= 1) s += __shfl_xor_sync(0xffffffffu, s, off);
    if (lane == 0) {
        float sv = s + g_Rb[b] * pb[d] - g_tb[b];
        g_pooled[b][d] = (g_prevsum[b][d] + lng[d] * sv) * (1.f / NN) + lnb[d];
    }
}

// ---------------- MLP head ----------------
__global__ void k_mlp1(const float* __restrict__ W1, const float* __restrict__ b1) {
    int warp = blockIdx.x * 8 + (threadIdx.x >> 5);
    int lane = threadIdx.x & 31;
    int b = warp >> 8, i = warp & 255;
    const float* w = W1 + (size_t)i * CC;
    float s = 0.f;
#pragma unroll 4
    for (int c = lane; c < CC; c += 32) s += w[c] * g_pooled[b][c];
#pragma unroll
    for (int off = 16; off > 0; off >>= 1) s += __shfl_xor_sync(0xffffffffu, s, off);
    if (lane == 0) g_h1[b][i] = fmaxf(s + b1[i], 0.f);
}

__global__ void k_mlp2(const float* __restrict__ W2, const float* __restrict__ b2) {
    int warp = blockIdx.x * 8 + (threadIdx.x >> 5);
    int lane = threadIdx.x & 31;
    int b = warp >> 8, i = warp & 255;
    const float* w = W2 + (size_t)i * HH;
    float s = 0.f;
#pragma unroll
    for (int c = lane; c < HH; c += 32) s += w[c] * g_h1[b][c];
#pragma unroll
    for (int off = 16; off > 0; off >>= 1) s += __shfl_xor_sync(0xffffffffu, s, off);
    if (lane == 0) g_h2[b][i] = fmaxf(s + b2[i], 0.f);
}

__global__ void k_mlp3(const float* __restrict__ W3, const float* __restrict__ b3,
                       float* __restrict__ out) {
    int warp = blockIdx.x * 8 + (threadIdx.x >> 5);
    int lane = threadIdx.x & 31;
    int b = warp / NCLS, j = warp % NCLS;
    const float* w = W3 + (size_t)j * HH;
    float s = 0.f;
#pragma unroll
    for (int c = lane; c < HH; c += 32) s += w[c] * g_h2[b][c];
#pragma unroll
    for (int off = 16; off > 0; off >>= 1) s += __shfl_xor_sync(0xffffffffu, s, off);
    if (lane == 0) out[b * NCLS + j] = s + b3[j];
}

// ---------------- launch ----------------
extern "C" void kernel_launch(void* const* d_in, const int* in_sizes, int n_in,
                              void* d_out, int out_size) {
    (void)in_sizes; (void)n_in; (void)out_size;
    const float* feat  = (const float*)d_in[0];
    const float* prev  = (const float*)d_in[1];
    // d_in[2], d_in[3] (positions) provably unused: gather is a row permutation
    // and all downstream consumers are permutation-invariant.
    const float* projW = (const float*)d_in[4];
    const float* projb = (const float*)d_in[5];
    const float* lng   = (const float*)d_in[6];
    const float* lnb   = (const float*)d_in[7];
    const float* W1    = (const float*)d_in[8];
    const float* b1    = (const float*)d_in[9];
    const float* W2    = (const float*)d_in[10];
    const float* b2    = (const float*)d_in[11];
    const float* W3    = (const float*)d_in[12];
    const float* b3    = (const float*)d_in[13];
    float* out = (float*)d_out;

    __nv_bfloat16* featb; cudaGetSymbolAddress((void**)&featb, g_featb);
    __nv_bfloat16* Wb;    cudaGetSymbolAddress((void**)&Wb, g_Wb);

    cudaFuncSetAttribute(k_gemm, cudaFuncAttributeMaxDynamicSharedMemorySize,
                         SMEM_NEED);

    k_init<<<MTOT / 256, 256>>>();
    k_cvt<<<(MTOT * CC / 4 + 255) / 256, 256>>>(feat, featb, MTOT * CC / 4);
    k_cvt<<<(CC * CC / 4 + 255) / 256, 256>>>(projW, Wb, CC * CC / 4);
    k_prev<<<dim3(32, 8), 512>>>(prev);
    k_gemm<<<dim3(MTOT / 128, CC / 128), 256, SMEM_NEED>>>(projb);
    k_stats<<<MTOT / 256, 256>>>();
    k_v<<<dim3(32, 8), 512>>>(feat);
    k_pool<<<512, 256>>>(projW, projb, lng, lnb);
    k_mlp1<<<256, 256>>>(W1, b1);
    k_mlp2<<<256, 256>>>(W2, b2);
    k_mlp3<<<1000, 256>>>(W3, b3, out);
}